// round 5
// baseline (speedup 1.0000x reference)
#include <cuda_runtime.h>
#include <cuda_fp16.h>

// HDBLUT 2x superresolution, GB300 sm_103a. Round 5:
//  - no prefetch (R4 showed it neutral/negative)
//  - 6 independent LDS.64 issued per rotation (both pixels batched)
//  - rotation permutation done in half2 domain via PRMT; single final
//    half2->float2 convert per output pair (cuts fma-pipe ~45%)
//  - fp16 LUT (1/3 folded) in 96KB smem, 2 CTAs/SM x 512 thr, nibble image

#define NN 2048
#define NTILES (1024 * 64)        // row-pairs x 32-col tiles
#define THREADS 512
#define WARPS_PER_CTA (THREADS / 32)
#define LUT_E (3 * 4096)
#define PSTRIDE 260
#define PWORDS 257
#define SMEM_BYTES (LUT_E * 8)

__device__ __align__(16) uint2 g_lut[LUT_E];   // half4 per entry, 96 KB
__device__ unsigned g_pimg[NN * PSTRIDE];      // nibble-packed image

__device__ __forceinline__ int refl(int t) {
    t = (t < 0) ? -t : t;
    return (t >= NN) ? (2 * NN - 2 - t) : t;
}

__device__ __forceinline__ unsigned hadd2u(unsigned a, unsigned b) {
    __half2 r = __hadd2(*reinterpret_cast<__half2*>(&a),
                        *reinterpret_cast<__half2*>(&b));
    return *reinterpret_cast<unsigned*>(&r);
}

__global__ void hdblut_prelude(const int* __restrict__ img,
                               const float4* __restrict__ w)
{
    int gid = blockIdx.x * blockDim.x + threadIdx.x;
    if (gid < LUT_E) {
        float4 v = w[gid];
        const float s = 1.0f / 3.0f;
        __half2 lo = __floats2half2_rn(v.x * s, v.y * s);
        __half2 hi = __floats2half2_rn(v.z * s, v.w * s);
        uint2 u;
        u.x = *reinterpret_cast<unsigned*>(&lo);
        u.y = *reinterpret_cast<unsigned*>(&hi);
        g_lut[gid] = u;
    }
    int pid = gid - LUT_E;
    if (pid >= 0 && pid < NN * PWORDS) {
        int r  = pid / PWORDS;
        int wi = pid - r * PWORDS;
        const int* row = img + (size_t)r * NN;
        unsigned val = 0;
        #pragma unroll
        for (int j = 0; j < 8; j++) {
            int col = wi * 8 + j - 2;
            col = (col < 0) ? -col : col;
            col = (col >= NN) ? (2 * NN - 2 - col) : col;
            val |= (unsigned)(row[col] & 15) << (4 * j);
        }
        g_pimg[(size_t)r * PSTRIDE + wi] = val;
    }
}

__global__ __launch_bounds__(THREADS, 2)
void hdblut_main(float2* __restrict__ out)
{
    extern __shared__ uint2 slut[];   // 96 KB fp16 LUT

    {
        uint4*       s4 = reinterpret_cast<uint4*>(slut);
        const uint4* g4 = reinterpret_cast<const uint4*>(g_lut);
        for (int i = threadIdx.x; i < LUT_E / 2; i += THREADS)
            s4[i] = g4[i];
    }
    __syncthreads();

    const int warp = threadIdx.x >> 5;
    const int lane = threadIdx.x & 31;
    const int gwarp  = blockIdx.x * WARPS_PER_CTA + warp;
    const int nwarps = gridDim.x * WARPS_PER_CTA;

    for (int t = gwarp; t < NTILES; t += nwarps) {
        const int I  = (t >> 6) << 1;       // low-res row pair (I, I+1)
        const int Jb = (t & 63) << 5;

        // 6 packed rows I-2..I+3; nibble j of rc[i] = img col J-2+j (J=Jb+lane)
        unsigned rc[6];
        {
            const int pos = Jb + lane;
            const int wi  = pos >> 3;
            const int sh  = (pos & 7) * 4;
            #pragma unroll
            for (int i = 0; i < 6; i++) {
                const unsigned* pr = g_pimg + (size_t)refl(I - 2 + i) * PSTRIDE + wi;
                unsigned w0 = __ldg(pr);
                unsigned w1 = __ldg(pr + 1);
                rc[i] = __funnelshift_r(w0, w1, sh);
            }
        }

        #define NIB(i, j)  ((int)((rc[(i)] >> (4 * (j))) & 15u))

        const int a8_[2] = { NIB(2, 2) << 8, NIB(3, 2) << 8 };

        // per-pixel, per-rotation half2 partial sums: sA=(w0,w1), sB=(w2,w3)
        unsigned sA[2][4], sB[2][4];

        // One rotation, BOTH pixels: 6 indices, 6 back-to-back LDS.64, 4 trees.
        #define ROT(r, b0x,b0y,c0x,c0y, b1x,b1y,c1x,c1y, b2x,b2y,c2x,c2y) do {  \
            int i00_ = 0*4096 + a8_[0] + (NIB(2+(b0x),2+(b0y))<<4) + NIB(2+(c0x),2+(c0y)); \
            int i01_ = 1*4096 + a8_[0] + (NIB(2+(b1x),2+(b1y))<<4) + NIB(2+(c1x),2+(c1y)); \
            int i02_ = 2*4096 + a8_[0] + (NIB(2+(b2x),2+(b2y))<<4) + NIB(2+(c2x),2+(c2y)); \
            int i10_ = 0*4096 + a8_[1] + (NIB(3+(b0x),2+(b0y))<<4) + NIB(3+(c0x),2+(c0y)); \
            int i11_ = 1*4096 + a8_[1] + (NIB(3+(b1x),2+(b1y))<<4) + NIB(3+(c1x),2+(c1y)); \
            int i12_ = 2*4096 + a8_[1] + (NIB(3+(b2x),2+(b2y))<<4) + NIB(3+(c2x),2+(c2y)); \
            uint2 h00 = slut[i00_]; uint2 h01 = slut[i01_]; uint2 h02 = slut[i02_]; \
            uint2 h10 = slut[i10_]; uint2 h11 = slut[i11_]; uint2 h12 = slut[i12_]; \
            sA[0][r] = hadd2u(hadd2u(h00.x, h01.x), h02.x);                      \
            sB[0][r] = hadd2u(hadd2u(h00.y, h01.y), h02.y);                      \
            sA[1][r] = hadd2u(hadd2u(h10.x, h11.x), h12.x);                      \
            sB[1][r] = hadd2u(hadd2u(h10.y, h11.y), h12.y);                      \
        } while (0)

        // r = 0: offsets as-is
        ROT(0,  0, 1,  0, 2,   1, 1,  2, 2,   1, 2,  2, 1);
        // r = 1: (x,y) -> (y,-x)
        ROT(1,  1, 0,  2, 0,   1,-1,  2,-2,   2,-1,  1,-2);
        // r = 2: (x,y) -> (-x,-y)
        ROT(2,  0,-1,  0,-2,  -1,-1, -2,-2,  -1,-2, -2,-1);
        // r = 3: (x,y) -> (-y,x)
        ROT(3, -1, 0, -2, 0,  -1, 1, -2, 2,  -2, 1, -1, 2);

        #undef ROT
        #undef NIB

        // Combine rotations in half2 domain, permuting with PRMT:
        //   (o00,o01) = sA0 + (sB1.lo,sA1.lo) + swap(sB2) + (sA3.hi,sB3.hi)
        //   (o10,o11) = sB0 + (sB1.hi,sA1.hi) + swap(sA2) + (sA3.lo,sB3.lo)
        const int J = Jb + lane;
        const size_t base = (size_t)(2 * I) * 2048 + J;
        #pragma unroll
        for (int ro = 0; ro < 2; ro++) {
            unsigned u1 = __byte_perm(sB[ro][1], sA[ro][1], 0x5410);
            unsigned u2 = __byte_perm(sB[ro][2], sB[ro][2], 0x1032);
            unsigned u3 = __byte_perm(sA[ro][3], sB[ro][3], 0x7632);
            unsigned oA = hadd2u(hadd2u(sA[ro][0], u1), hadd2u(u2, u3));

            unsigned v1 = __byte_perm(sB[ro][1], sA[ro][1], 0x7632);
            unsigned v2 = __byte_perm(sA[ro][2], sA[ro][2], 0x1032);
            unsigned v3 = __byte_perm(sA[ro][3], sB[ro][3], 0x5410);
            unsigned oB = hadd2u(hadd2u(sB[ro][0], v1), hadd2u(v2, v3));

            float2 fA = __half22float2(*reinterpret_cast<__half2*>(&oA));
            float2 fB = __half22float2(*reinterpret_cast<__half2*>(&oB));
            out[base + (size_t)(2 * ro)     * 2048] = fA;
            out[base + (size_t)(2 * ro + 1) * 2048] = fB;
        }
    }
}

extern "C" void kernel_launch(void* const* d_in, const int* in_sizes, int n_in,
                              void* d_out, int out_size)
{
    const int*    img  = (const int*)d_in[0];
    const float4* wlut = (const float4*)d_in[1];
    float2*       out  = (float2*)d_out;

    int sms = 0;
    cudaDeviceGetAttribute(&sms, cudaDevAttrMultiProcessorCount, 0);
    if (sms <= 0) sms = 148;

    int total = LUT_E + NN * PWORDS;
    hdblut_prelude<<<(total + 255) / 256, 256>>>(img, wlut);

    cudaFuncSetAttribute(hdblut_main,
                         cudaFuncAttributeMaxDynamicSharedMemorySize, SMEM_BYTES);
    hdblut_main<<<2 * sms, THREADS, SMEM_BYTES>>>(out);
}